// round 3
// baseline (speedup 1.0000x reference)
#include <cuda_runtime.h>
#include <cuda_bf16.h>

#define SQRT5F 2.23606797749978969f

// Output: out[i][a][j][b], i in [0,n), j in [0,m), a,b in [0,8)
// k[i,a,j,b] = c^2 * ( A(i,j)*inv_l2[a]*delta(a,b) - 5*fr(i,j)*D[i,j,a]*D[i,j,b] )
// with r = || (X1_i - X2_j)/l ||, fr = (5/3) exp(-sqrt5 r), A = fr (1 + sqrt5 r),
// D[i,j,k] = (X1_i[k]-X2_j[k]) * inv_l2[k].

__global__ __launch_bounds__(256, 4)
void deriv2_matern52_kernel(const float* __restrict__ X1,
                            const float* __restrict__ X2,
                            const float* __restrict__ c_ptr,
                            const float* __restrict__ l,
                            float* __restrict__ out,
                            int n, int m) {
    constexpr int D = 8;

    const int tid = blockIdx.x * blockDim.x + threadIdx.x;
    const int i = tid / m;          // X1 row
    const int j = tid - i * m;      // X2 row
    if (i >= n) return;

    // Per-row constants: tiny (9 floats), L1-resident after first wave.
    float il2[D];
    float x1r[D];
    {
        const float4* lv4 = reinterpret_cast<const float4*>(l);
        float4 la = lv4[0], lb = lv4[1];
        float lr[D] = {la.x, la.y, la.z, la.w, lb.x, lb.y, lb.z, lb.w};
#pragma unroll
        for (int k = 0; k < D; ++k) il2[k] = 1.0f / (lr[k] * lr[k]);

        const float4* x1v = reinterpret_cast<const float4*>(X1 + (size_t)i * D);
        float4 xa = x1v[0], xb = x1v[1];
        x1r[0] = xa.x; x1r[1] = xa.y; x1r[2] = xa.z; x1r[3] = xa.w;
        x1r[4] = xb.x; x1r[5] = xb.y; x1r[6] = xb.z; x1r[7] = xb.w;
    }
    const float cv = __ldg(c_ptr);
    const float c2 = cv * cv;

    // Load X2 row j (8 floats) as two float4: consecutive threads ->
    // consecutive 32B rows -> coalesced.
    const float4* x2v = reinterpret_cast<const float4*>(X2 + (size_t)j * D);
    float4 x2a = x2v[0];
    float4 x2b = x2v[1];
    float x2r[D] = {x2a.x, x2a.y, x2a.z, x2a.w, x2b.x, x2b.y, x2b.z, x2b.w};

    float Dv[D];
    float r2 = 0.0f;
#pragma unroll
    for (int k = 0; k < D; ++k) {
        float dx = x1r[k] - x2r[k];
        Dv[k] = dx * il2[k];          // D[i,j,k]
        r2 = fmaf(dx, Dv[k], r2);     // dx^2 * inv_l2
    }

    const float r  = sqrtf(r2);
    const float fr = (5.0f / 3.0f) * __expf(-SQRT5F * r);
    const float A  = fr * fmaf(SQRT5F, r, 1.0f);

    const float Ac   = A * c2;          // coefficient of diagonal term
    const float m5fc = -5.0f * fr * c2; // coefficient of outer-product term

    // out base for (i, a=0, j, b=0); a-stride = m*D, b contiguous.
    float* base = out + ((size_t)i * D * m + j) * D;
    const size_t a_stride = (size_t)m * D;

    // Materialize the whole 8x8 block first so the 16 stores are
    // dependency-free and can queue back-to-back at the LSU.
    float4 w[D][2];
#pragma unroll
    for (int a = 0; a < D; ++a) {
        const float fa = m5fc * Dv[a];
        float v[D];
#pragma unroll
        for (int b = 0; b < D; ++b) {
            v[b] = fa * Dv[b];
        }
        v[a] = fmaf(Ac, il2[a], v[a]);  // add diagonal term
        w[a][0] = make_float4(v[0], v[1], v[2], v[3]);
        w[a][1] = make_float4(v[4], v[5], v[6], v[7]);
    }

#pragma unroll
    for (int a = 0; a < D; ++a) {
        float4* dst = reinterpret_cast<float4*>(base + a * a_stride);
        // Streaming stores: 256MB write-once output, keep it out of L2.
        __stcs(dst + 0, w[a][0]);
        __stcs(dst + 1, w[a][1]);
    }
}

extern "C" void kernel_launch(void* const* d_in, const int* in_sizes, int n_in,
                              void* d_out, int out_size) {
    // Expected metadata order: X1 [n*d], X2 [m*d], c [1], l [d].
    // Derive robustly: c is the size-1 input among {2,3}; l is the other.
    const float* X1 = (const float*)d_in[0];
    const float* X2 = (const float*)d_in[1];
    const float* c;
    const float* l;
    int d;
    if (in_sizes[2] == 1) {
        c = (const float*)d_in[2];
        l = (const float*)d_in[3];
        d = in_sizes[3];
    } else {
        l = (const float*)d_in[2];
        c = (const float*)d_in[3];
        d = in_sizes[2];
    }
    float* out = (float*)d_out;

    const int n = in_sizes[0] / d;      // 1024
    const int m = in_sizes[1] / d;      // 1024

    const int TPB = 256;
    const long long total = (long long)n * m;
    const int blocks = (int)((total + TPB - 1) / TPB);
    deriv2_matern52_kernel<<<blocks, TPB>>>(X1, X2, c, l, out, n, m);
}

// round 4
// speedup vs baseline: 1.7182x; 1.7182x over previous
#include <cuda_runtime.h>
#include <cuda_bf16.h>

#define SQRT5F 2.23606797749978969f

// Output: out[i][a][j][b], i in [0,n), j in [0,m), a,b in [0,8)
// k[i,a,j,b] = c^2 * ( A(i,j)*inv_l2[a]*delta(a,b) - 5*fr(i,j)*D[i,j,a]*D[i,j,b] )
//
// Mapping: TWO lanes per (i,j) pair. Lane t -> pair p = t>>1, half h = t&1
// (covers b in [4h, 4h+4)). For each a, a lane stores ONE float4 at
// base_a + lane*16B, so every STG.128 instruction's 32 lanes cover 512B of
// fully contiguous memory -> full-line L1 wavefronts (4 per STG instead of 8
// half-utilized ones in the previous version).

__global__ __launch_bounds__(256, 8)
void deriv2_matern52_kernel(const float* __restrict__ X1,
                            const float* __restrict__ X2,
                            const float* __restrict__ c_ptr,
                            const float* __restrict__ l,
                            float* __restrict__ out,
                            int n, int m) {
    constexpr int D = 8;

    const int t = blockIdx.x * blockDim.x + threadIdx.x;
    const int p = t >> 1;           // pair index
    const int h = t & 1;            // b-half: 0 -> b 0..3, 1 -> b 4..7
    const int i = p / m;
    const int j = p - i * m;
    if (i >= n) return;

    // Tiny constants; L1-resident after first touch.
    float il2[D];
    float x1r[D];
    {
        const float4* lv4 = reinterpret_cast<const float4*>(l);
        float4 la = lv4[0], lb = lv4[1];
        float lr[D] = {la.x, la.y, la.z, la.w, lb.x, lb.y, lb.z, lb.w};
#pragma unroll
        for (int k = 0; k < D; ++k) il2[k] = 1.0f / (lr[k] * lr[k]);

        const float4* x1v = reinterpret_cast<const float4*>(X1 + (size_t)i * D);
        float4 xa = x1v[0], xb = x1v[1];
        x1r[0] = xa.x; x1r[1] = xa.y; x1r[2] = xa.z; x1r[3] = xa.w;
        x1r[4] = xb.x; x1r[5] = xb.y; x1r[6] = xb.z; x1r[7] = xb.w;
    }
    const float cv = __ldg(c_ptr);
    const float c2 = cv * cv;

    // X2 row j: both lanes of a pair load the same 32B (L1 broadcast).
    const float4* x2v = reinterpret_cast<const float4*>(X2 + (size_t)j * D);
    float4 x2a = x2v[0];
    float4 x2b = x2v[1];
    float x2r[D] = {x2a.x, x2a.y, x2a.z, x2a.w, x2b.x, x2b.y, x2b.z, x2b.w};

    float Dv[D];
    float r2 = 0.0f;
#pragma unroll
    for (int k = 0; k < D; ++k) {
        float dx = x1r[k] - x2r[k];
        Dv[k] = dx * il2[k];
        r2 = fmaf(dx, Dv[k], r2);
    }

    const float r  = sqrtf(r2);
    const float fr = (5.0f / 3.0f) * __expf(-SQRT5F * r);
    const float A  = fr * fmaf(SQRT5F, r, 1.0f);

    const float Ac   = A * c2;
    const float m5fc = -5.0f * fr * c2;

    // This lane's b-half of Dv, chosen with selects (no dynamic reg indexing).
    float Dh[4];
#pragma unroll
    for (int b4 = 0; b4 < 4; ++b4) {
        Dh[b4] = h ? Dv[b4 + 4] : Dv[b4];
    }
    const int bbase = h << 2;

    // Base address for (i, a=0, j, b=4h). a-stride = m*D floats.
    float* base = out + (((size_t)i * D * m + j) * D + bbase);
    const size_t a_stride = (size_t)m * D;

#pragma unroll
    for (int a = 0; a < D; ++a) {
        const float fa = m5fc * Dv[a];
        float v0 = fa * Dh[0];
        float v1 = fa * Dh[1];
        float v2 = fa * Dh[2];
        float v3 = fa * Dh[3];
        // Diagonal term: b == a. b = bbase + b4; a is compile-time constant.
        const float diag = Ac * il2[a];
        if (bbase + 0 == a) v0 += diag;
        if (bbase + 1 == a) v1 += diag;
        if (bbase + 2 == a) v2 += diag;
        if (bbase + 3 == a) v3 += diag;
        // Streaming store: write-once 256MB output, keep out of L2.
        __stcs(reinterpret_cast<float4*>(base + a * a_stride),
               make_float4(v0, v1, v2, v3));
    }
}

extern "C" void kernel_launch(void* const* d_in, const int* in_sizes, int n_in,
                              void* d_out, int out_size) {
    // Expected metadata order: X1 [n*d], X2 [m*d], c [1], l [d].
    const float* X1 = (const float*)d_in[0];
    const float* X2 = (const float*)d_in[1];
    const float* c;
    const float* l;
    int d;
    if (in_sizes[2] == 1) {
        c = (const float*)d_in[2];
        l = (const float*)d_in[3];
        d = in_sizes[3];
    } else {
        l = (const float*)d_in[2];
        c = (const float*)d_in[3];
        d = in_sizes[2];
    }
    float* out = (float*)d_out;

    const int n = in_sizes[0] / d;      // 1024
    const int m = in_sizes[1] / d;      // 1024

    const int TPB = 256;
    const long long total = (long long)n * m * 2;  // 2 lanes per pair
    const int blocks = (int)((total + TPB - 1) / TPB);
    deriv2_matern52_kernel<<<blocks, TPB>>>(X1, X2, c, l, out, n, m);
}